// round 5
// baseline (speedup 1.0000x reference)
#include <cuda_runtime.h>

#define NTHREADS 512
#define ROWS_PER_CTA 64
#define NCTA 128          // 8192 / 64
#define OUTSTR 771        // 257*3

// Thread layout: u = tid>>3 (hidden unit 0..63), pb = tid&7 (row-block 0..7).
// Thread owns 8 rows = 4 float2 pairs: global pairs pb*4..pb*4+3.
struct SMem {
    float4 wpack[76][64];    // wpack[k][u] = {Wi,Wf,Wg,Wo}[.,k] for unit u   (77824 B)
    float4 xA[2][76][8];     // [phase][k][pb]: pairs 4pb,4pb+1               (19456 B)
    float4 xB[2][76][8];     // [phase][k][pb]: pairs 4pb+2,4pb+3             (19456 B)
    float  w1t[64][64];      // w1t[k][u] = W1[u][k]                          (16384 B)
    float2 zpart[16][8][4];  // [warp][pb][pair]                              (4096 B)
    float2 dpbuf[8][4];      // [pb][pair] dp values                          (256 B)
};

__device__ __forceinline__ float sigf(float x) {
    return __fdividef(1.f, 1.f + __expf(-x));
}
__device__ __forceinline__ float tanh_(float x) {
    float e = __expf(2.f * x);
    return 1.f - __fdividef(2.f, e + 1.f);
}

// 4 accumulators += pair-vector * scalar, via packed fma.rn.f32x2
__device__ __forceinline__ void gate4(float sw,
                                      float2 p0, float2 p1, float2 p2, float2 p3,
                                      float2& a0, float2& a1, float2& a2, float2& a3) {
    asm("{\n\t"
        ".reg .b64 rb, rx, ra;\n\t"
        "mov.b64 rb, {%8,%8};\n\t"
        "mov.b64 rx, {%9,%10};  mov.b64 ra, {%0,%1}; fma.rn.f32x2 ra, rx, rb, ra; mov.b64 {%0,%1}, ra;\n\t"
        "mov.b64 rx, {%11,%12}; mov.b64 ra, {%2,%3}; fma.rn.f32x2 ra, rx, rb, ra; mov.b64 {%2,%3}, ra;\n\t"
        "mov.b64 rx, {%13,%14}; mov.b64 ra, {%4,%5}; fma.rn.f32x2 ra, rx, rb, ra; mov.b64 {%4,%5}, ra;\n\t"
        "mov.b64 rx, {%15,%16}; mov.b64 ra, {%6,%7}; fma.rn.f32x2 ra, rx, rb, ra; mov.b64 {%6,%7}, ra;\n\t"
        "}"
        : "+f"(a0.x), "+f"(a0.y), "+f"(a1.x), "+f"(a1.y),
          "+f"(a2.x), "+f"(a2.y), "+f"(a3.x), "+f"(a3.y)
        : "f"(sw),
          "f"(p0.x), "f"(p0.y), "f"(p1.x), "f"(p1.y),
          "f"(p2.x), "f"(p2.y), "f"(p3.x), "f"(p3.y));
}

// LSTM cell: k=2 (x2) and k=3 (x3) come from registers, rest from SMEM phase ph.
__device__ __forceinline__ void lstm_step4(const SMem* s, int u, int pb, int ph,
                                           const float2 x2[4], const float2 x3[4],
                                           float bi, float bf, float bg, float bo,
                                           float2 c4[4], float2 h4[4]) {
    float2 ai[4], af4[4], ag[4], ao[4];
#pragma unroll
    for (int p = 0; p < 4; ++p) {
        ai[p] = make_float2(bi, bi);
        af4[p] = make_float2(bf, bf);
        ag[p] = make_float2(bg, bg);
        ao[p] = make_float2(bo, bo);
    }
    const float4* wp = &s->wpack[0][u];
    const float4* xa = &s->xA[ph][0][pb];
    const float4* xb = &s->xB[ph][0][pb];

    auto doK = [&](float4 w, float4 A, float4 B) {
        float2 p0 = make_float2(A.x, A.y), p1 = make_float2(A.z, A.w);
        float2 p2 = make_float2(B.x, B.y), p3 = make_float2(B.z, B.w);
        gate4(w.x, p0, p1, p2, p3, ai[0], ai[1], ai[2], ai[3]);
        gate4(w.y, p0, p1, p2, p3, af4[0], af4[1], af4[2], af4[3]);
        gate4(w.z, p0, p1, p2, p3, ag[0], ag[1], ag[2], ag[3]);
        gate4(w.w, p0, p1, p2, p3, ao[0], ao[1], ao[2], ao[3]);
    };

    doK(wp[0], xa[0], xb[0]);        // k=0
    doK(wp[64], xa[8], xb[8]);       // k=1
    {                                // k=2 (register operand)
        float4 w = wp[2 * 64];
        gate4(w.x, x2[0], x2[1], x2[2], x2[3], ai[0], ai[1], ai[2], ai[3]);
        gate4(w.y, x2[0], x2[1], x2[2], x2[3], af4[0], af4[1], af4[2], af4[3]);
        gate4(w.z, x2[0], x2[1], x2[2], x2[3], ag[0], ag[1], ag[2], ag[3]);
        gate4(w.w, x2[0], x2[1], x2[2], x2[3], ao[0], ao[1], ao[2], ao[3]);
    }
    {                                // k=3 (register operand, dist)
        float4 w = wp[3 * 64];
        gate4(w.x, x3[0], x3[1], x3[2], x3[3], ai[0], ai[1], ai[2], ai[3]);
        gate4(w.y, x3[0], x3[1], x3[2], x3[3], af4[0], af4[1], af4[2], af4[3]);
        gate4(w.z, x3[0], x3[1], x3[2], x3[3], ag[0], ag[1], ag[2], ag[3]);
        gate4(w.w, x3[0], x3[1], x3[2], x3[3], ao[0], ao[1], ao[2], ao[3]);
    }
#pragma unroll 4
    for (int k = 4; k < 76; ++k)
        doK(wp[k * 64], xa[k * 8], xb[k * 8]);

#pragma unroll
    for (int p = 0; p < 4; ++p) {
        float ix = sigf(ai[p].x), fx = sigf(af4[p].x), gx = tanh_(ag[p].x), ox = sigf(ao[p].x);
        c4[p].x = fmaf(fx, c4[p].x, ix * gx);
        h4[p].x = ox * tanh_(c4[p].x);
        float iy = sigf(ai[p].y), fy = sigf(af4[p].y), gy = tanh_(ag[p].y), oy = sigf(ao[p].y);
        c4[p].y = fmaf(fy, c4[p].y, iy * gy);
        h4[p].y = oy * tanh_(c4[p].y);
    }
}

__global__ void __launch_bounds__(NTHREADS, 1)
lstm_fused(const float* __restrict__ noise, const float* __restrict__ hist,
           const float* __restrict__ gap,   const float* __restrict__ W_ih,
           const float* __restrict__ W_hh,  const float* __restrict__ b_ih,
           const float* __restrict__ b_hh,  const float* __restrict__ W1,
           const float* __restrict__ b1,    const float* __restrict__ W2,
           const float* __restrict__ b2,    float* __restrict__ out) {
    extern __shared__ char smraw[];
    SMem* s = reinterpret_cast<SMem*>(smraw);

    const int tid = threadIdx.x;
    const int u   = tid >> 3;      // hidden unit
    const int pb  = tid & 7;       // row-block
    const int wid = tid >> 5;
    const int lane = tid & 31;
    const int blockRow = blockIdx.x * ROWS_PER_CTA;
    const int R = blockRow + pb * 8;   // this thread's rows: R..R+7

    // ---- stage weights (transposed, gate-packed) ----
    for (int idx = tid; idx < 76 * 64; idx += NTHREADS) {
        int k = idx >> 6, uu = idx & 63;
        float4 w;
        if (k < 12) {
            w.x = W_ih[uu * 12 + k];
            w.y = W_ih[(64 + uu) * 12 + k];
            w.z = W_ih[(128 + uu) * 12 + k];
            w.w = W_ih[(192 + uu) * 12 + k];
        } else {
            int kk = k - 12;
            w.x = W_hh[uu * 64 + kk];
            w.y = W_hh[(64 + uu) * 64 + kk];
            w.z = W_hh[(128 + uu) * 64 + kk];
            w.w = W_hh[(192 + uu) * 64 + kk];
        }
        s->wpack[k][uu] = w;
    }
    for (int idx = tid; idx < 64 * 64; idx += NTHREADS) {
        int uu = idx >> 6, k = idx & 63;
        s->w1t[k][uu] = W1[idx];
    }
    // h0 = 0 in phase 0
    for (int idx = tid; idx < 64 * 8; idx += NTHREADS) {
        int k = idx >> 3, b = idx & 7;
        s->xA[0][12 + k][b] = make_float4(0.f, 0.f, 0.f, 0.f);
        s->xB[0][12 + k][b] = make_float4(0.f, 0.f, 0.f, 0.f);
    }
    // ---- copy hist_x into out[:, :64, :] ----
    for (int idx = tid; idx < ROWS_PER_CTA * 192; idx += NTHREADS) {
        int rl = idx / 192, j = idx % 192;
        out[(size_t)(blockRow + rl) * OUTSTR + j] = hist[(size_t)(blockRow + rl) * 192 + j];
    }

    const float bi = b_ih[u] + b_hh[u];
    const float bf = b_ih[64 + u] + b_hh[64 + u];
    const float bg = b_ih[128 + u] + b_hh[128 + u];
    const float bo = b_ih[192 + u] + b_hh[192 + u];
    const float b1v = b1[u];
    const float w2v = W2[u];
    const float b2v = b2[0];

    float2 c4[4], h4[4], dist4[4], pfv[4], pfd[4];
#pragma unroll
    for (int p = 0; p < 4; ++p) {
        c4[p] = make_float2(0.f, 0.f);
        dist4[p] = make_float2(0.f, 0.f);
        pfv[p] = make_float2(0.f, 0.f);
        pfd[p] = make_float2(0.f, 0.f);
    }

    // Prefetch: pfd = hist ch2 (all threads, drives dist), pfv = this u's channel
    auto pre_cond = [&](int j) {
#pragma unroll
        for (int p = 0; p < 4; ++p) {
            const float* hp = hist + (size_t)(R + 2 * p) * 192 + j * 3;
            pfd[p].x = hp[2];
            pfd[p].y = hp[192 + 2];
            if (u < 2) {
                pfv[p].x = hp[u];
                pfv[p].y = hp[192 + u];
            }
        }
        if (u >= 4 && u < 12) {
            int ch = u - 4;
#pragma unroll
            for (int p = 0; p < 4; ++p) {
                const float* np = noise + (size_t)(R + 2 * p) * 2048 + j * 8 + ch;
                pfv[p].x = np[0];
                pfv[p].y = np[2048];
            }
        }
    };
    auto pre_gen = [&](int t) {
        if (u < 2) {
#pragma unroll
            for (int p = 0; p < 4; ++p) {
                const float* gp = gap + (size_t)(R + 2 * p) * 386 + t * 2 + u;
                pfv[p].x = gp[0];
                pfv[p].y = gp[386];
            }
        } else if (u >= 4 && u < 12) {
            if (t < 192) {
                int ch = u - 4;
#pragma unroll
                for (int p = 0; p < 4; ++p) {
                    const float* np = noise + (size_t)(R + 2 * p) * 2048 + (64 + t) * 8 + ch;
                    pfv[p].x = np[0];
                    pfv[p].y = np[2048];
                }
            } else {
#pragma unroll
                for (int p = 0; p < 4; ++p) pfv[p] = make_float2(0.f, 0.f);
            }
        }
    };
    auto write_inputs = [&](int ph) {
        if (u < 2 || (u >= 4 && u < 12)) {
            s->xA[ph][u][pb] = make_float4(pfv[0].x, pfv[0].y, pfv[1].x, pfv[1].y);
            s->xB[ph][u][pb] = make_float4(pfv[2].x, pfv[2].y, pfv[3].x, pfv[3].y);
        }
    };
    auto write_h = [&](int ph) {
        s->xA[ph][12 + u][pb] = make_float4(h4[0].x, h4[0].y, h4[1].x, h4[1].y);
        s->xB[ph][12 + u][pb] = make_float4(h4[2].x, h4[2].y, h4[3].x, h4[3].y);
    };

    pre_cond(0);
    __syncthreads();   // staging + h0 visible

    // ================= conditioning (64 steps, 1 barrier each) =================
    for (int j = 0; j < 64; ++j) {
        int ph = j & 1;
        write_inputs(ph);
        float2 x2[4];
#pragma unroll
        for (int p = 0; p < 4; ++p) {
            x2[p] = pfd[p];                 // hist ch2 (k=2 input)
            dist4[p].x += pfd[p].x;         // inclusive cumsum (k=3 input)
            dist4[p].y += pfd[p].y;
        }
        __syncthreads();                    // inputs + previous h visible
        if (j < 63) pre_cond(j + 1); else pre_gen(0);
        lstm_step4(s, u, pb, ph, x2, dist4, bi, bf, bg, bo, c4, h4);
        write_h(ph ^ 1);
    }
    __syncthreads();   // last h write visible for gen MLP

    // ================= generation (193 steps, 3 barriers each) =================
    for (int t = 0; t <= 192; ++t) {
        int ph = t & 1;
        // --- MLP head: a[u][row] = b1 + sum_k h[k][row]*W1[u][k] ---
        float2 a0 = make_float2(b1v, b1v), a1v = a0, a2 = a0, a3 = a0;
        {
            const float*  w1p = &s->w1t[0][u];
            const float4* ha  = &s->xA[ph][12][pb];
            const float4* hb  = &s->xB[ph][12][pb];
#pragma unroll 4
            for (int k = 0; k < 64; ++k) {
                float wv = w1p[k * 64];
                float4 A = ha[k * 8], B = hb[k * 8];
                gate4(wv, make_float2(A.x, A.y), make_float2(A.z, A.w),
                      make_float2(B.x, B.y), make_float2(B.z, B.w),
                      a0, a1v, a2, a3);
            }
        }
        float2 part[4];
        part[0] = make_float2(tanh_(a0.x) * w2v, tanh_(a0.y) * w2v);
        part[1] = make_float2(tanh_(a1v.x) * w2v, tanh_(a1v.y) * w2v);
        part[2] = make_float2(tanh_(a2.x) * w2v, tanh_(a2.y) * w2v);
        part[3] = make_float2(tanh_(a3.x) * w2v, tanh_(a3.y) * w2v);
        // reduce over the 4 u's in this warp (lane bits 3,4)
#pragma unroll
        for (int p = 0; p < 4; ++p) {
            part[p].x += __shfl_xor_sync(0xffffffffu, part[p].x, 8);
            part[p].y += __shfl_xor_sync(0xffffffffu, part[p].y, 8);
            part[p].x += __shfl_xor_sync(0xffffffffu, part[p].x, 16);
            part[p].y += __shfl_xor_sync(0xffffffffu, part[p].y, 16);
        }
        if (lane < 8) {
#pragma unroll
            for (int p = 0; p < 4; ++p) s->zpart[wid][pb][p] = part[p];
        }
        write_inputs(ph);                   // gap/noise for this step
        __syncthreads();                    // B: zpart + inputs ready
        if (tid < 32) {
            int pb2 = tid >> 2, p2 = tid & 3;
            float sx = b2v, sy = b2v;
#pragma unroll
            for (int w = 0; w < 16; ++w) {
                float2 z = s->zpart[w][pb2][p2];
                sx += z.x; sy += z.y;
            }
            s->dpbuf[pb2][p2] = make_float2(24.f * tanh_(sx), 24.f * tanh_(sy));
        }
        __syncthreads();                    // C: dp ready
        float2 dp[4];
#pragma unroll
        for (int p = 0; p < 4; ++p) {
            dp[p] = s->dpbuf[pb][p];
            dist4[p].x += dp[p].x;
            dist4[p].y += dp[p].y;
        }
        int trow = (64 + t) * 3;
        if (u < 2) {
#pragma unroll
            for (int p = 0; p < 4; ++p) {
                out[(size_t)(R + 2 * p) * OUTSTR + trow + u] = pfv[p].x;
                out[(size_t)(R + 2 * p + 1) * OUTSTR + trow + u] = pfv[p].y;
            }
        } else if (u == 2) {
#pragma unroll
            for (int p = 0; p < 4; ++p) {
                out[(size_t)(R + 2 * p) * OUTSTR + trow + 2] = dp[p].x;
                out[(size_t)(R + 2 * p + 1) * OUTSTR + trow + 2] = dp[p].y;
            }
        }
        if (t == 192) break;                // last LSTM update is dead in the reference
        pre_gen(t + 1);
        lstm_step4(s, u, pb, ph, dp, dist4, bi, bf, bg, bo, c4, h4);
        write_h(ph ^ 1);
        __syncthreads();                    // D: h visible for next MLP
    }
}

extern "C" void kernel_launch(void* const* d_in, const int* in_sizes, int n_in,
                              void* d_out, int out_size) {
    const float* noise = (const float*)d_in[0];
    const float* hist  = (const float*)d_in[1];
    const float* gap   = (const float*)d_in[2];
    const float* W_ih  = (const float*)d_in[3];
    const float* W_hh  = (const float*)d_in[4];
    const float* b_ih  = (const float*)d_in[5];
    const float* b_hh  = (const float*)d_in[6];
    const float* W1    = (const float*)d_in[7];
    const float* b1    = (const float*)d_in[8];
    const float* W2    = (const float*)d_in[9];
    const float* b2    = (const float*)d_in[10];
    float* out = (float*)d_out;

    size_t smem = sizeof(SMem);
    cudaFuncSetAttribute(lstm_fused, cudaFuncAttributeMaxDynamicSharedMemorySize, (int)smem);
    lstm_fused<<<NCTA, NTHREADS, smem>>>(noise, hist, gap, W_ih, W_hh, b_ih, b_hh,
                                         W1, b1, W2, b2, out);
}

// round 6
// speedup vs baseline: 1.0024x; 1.0024x over previous
#include <cuda_runtime.h>

#define NTHREADS 512
#define ROWS_PER_CTA 64
#define NCTA 128          // 8192 / 64
#define OUTSTR 771        // 257*3

// Thread layout: u = tid>>3 (hidden unit 0..63), pb = tid&7 (row-block 0..7).
// Thread owns 8 rows = 4 float2 pairs: global pairs pb*4..pb*4+3.
struct SMem {
    float4 wpack[76][64];    // wpack[k][u] = {Wi,Wf,Wg,Wo}[.,k] for unit u   (77824 B)
    float4 xA[2][76][8];     // [phase][k][pb]: pairs 4pb,4pb+1               (19456 B)
    float4 xB[2][76][8];     // [phase][k][pb]: pairs 4pb+2,4pb+3             (19456 B)
    float  w1t[64][64];      // w1t[k][u] = W1[u][k]                          (16384 B)
    float2 zpart[16][8][4];  // [warp][pb][pair]                              (4096 B)
    float2 dpbuf[8][4];      // [pb][pair] dp values                          (256 B)
};

__device__ __forceinline__ float sigf(float x) {
    return __fdividef(1.f, 1.f + __expf(-x));
}
__device__ __forceinline__ float tanh_(float x) {
    float e = __expf(2.f * x);
    return 1.f - __fdividef(2.f, e + 1.f);
}

// 4 accumulators += pair-vector * scalar, via packed fma.rn.f32x2
__device__ __forceinline__ void gate4(float sw,
                                      float2 p0, float2 p1, float2 p2, float2 p3,
                                      float2& a0, float2& a1, float2& a2, float2& a3) {
    asm("{\n\t"
        ".reg .b64 rb, rx, ra;\n\t"
        "mov.b64 rb, {%8,%8};\n\t"
        "mov.b64 rx, {%9,%10};  mov.b64 ra, {%0,%1}; fma.rn.f32x2 ra, rx, rb, ra; mov.b64 {%0,%1}, ra;\n\t"
        "mov.b64 rx, {%11,%12}; mov.b64 ra, {%2,%3}; fma.rn.f32x2 ra, rx, rb, ra; mov.b64 {%2,%3}, ra;\n\t"
        "mov.b64 rx, {%13,%14}; mov.b64 ra, {%4,%5}; fma.rn.f32x2 ra, rx, rb, ra; mov.b64 {%4,%5}, ra;\n\t"
        "mov.b64 rx, {%15,%16}; mov.b64 ra, {%6,%7}; fma.rn.f32x2 ra, rx, rb, ra; mov.b64 {%6,%7}, ra;\n\t"
        "}"
        : "+f"(a0.x), "+f"(a0.y), "+f"(a1.x), "+f"(a1.y),
          "+f"(a2.x), "+f"(a2.y), "+f"(a3.x), "+f"(a3.y)
        : "f"(sw),
          "f"(p0.x), "f"(p0.y), "f"(p1.x), "f"(p1.y),
          "f"(p2.x), "f"(p2.y), "f"(p3.x), "f"(p3.y));
}

// LSTM cell: k=2 (x2) and k=3 (x3) come from registers, rest from SMEM phase ph.
__device__ __forceinline__ void lstm_step4(const SMem* s, int u, int pb, int ph,
                                           const float2 x2[4], const float2 x3[4],
                                           float bi, float bf, float bg, float bo,
                                           float2 c4[4], float2 h4[4]) {
    float2 ai[4], af4[4], ag[4], ao[4];
#pragma unroll
    for (int p = 0; p < 4; ++p) {
        ai[p] = make_float2(bi, bi);
        af4[p] = make_float2(bf, bf);
        ag[p] = make_float2(bg, bg);
        ao[p] = make_float2(bo, bo);
    }
    const float4* wp = &s->wpack[0][u];
    const float4* xa = &s->xA[ph][0][pb];
    const float4* xb = &s->xB[ph][0][pb];

    auto doK = [&](float4 w, float4 A, float4 B) {
        float2 p0 = make_float2(A.x, A.y), p1 = make_float2(A.z, A.w);
        float2 p2 = make_float2(B.x, B.y), p3 = make_float2(B.z, B.w);
        gate4(w.x, p0, p1, p2, p3, ai[0], ai[1], ai[2], ai[3]);
        gate4(w.y, p0, p1, p2, p3, af4[0], af4[1], af4[2], af4[3]);
        gate4(w.z, p0, p1, p2, p3, ag[0], ag[1], ag[2], ag[3]);
        gate4(w.w, p0, p1, p2, p3, ao[0], ao[1], ao[2], ao[3]);
    };

    doK(wp[0], xa[0], xb[0]);        // k=0
    doK(wp[64], xa[8], xb[8]);       // k=1
    {                                // k=2 (register operand)
        float4 w = wp[2 * 64];
        gate4(w.x, x2[0], x2[1], x2[2], x2[3], ai[0], ai[1], ai[2], ai[3]);
        gate4(w.y, x2[0], x2[1], x2[2], x2[3], af4[0], af4[1], af4[2], af4[3]);
        gate4(w.z, x2[0], x2[1], x2[2], x2[3], ag[0], ag[1], ag[2], ag[3]);
        gate4(w.w, x2[0], x2[1], x2[2], x2[3], ao[0], ao[1], ao[2], ao[3]);
    }
    {                                // k=3 (register operand, dist)
        float4 w = wp[3 * 64];
        gate4(w.x, x3[0], x3[1], x3[2], x3[3], ai[0], ai[1], ai[2], ai[3]);
        gate4(w.y, x3[0], x3[1], x3[2], x3[3], af4[0], af4[1], af4[2], af4[3]);
        gate4(w.z, x3[0], x3[1], x3[2], x3[3], ag[0], ag[1], ag[2], ag[3]);
        gate4(w.w, x3[0], x3[1], x3[2], x3[3], ao[0], ao[1], ao[2], ao[3]);
    }
#pragma unroll 4
    for (int k = 4; k < 76; ++k)
        doK(wp[k * 64], xa[k * 8], xb[k * 8]);

#pragma unroll
    for (int p = 0; p < 4; ++p) {
        float ix = sigf(ai[p].x), fx = sigf(af4[p].x), gx = tanh_(ag[p].x), ox = sigf(ao[p].x);
        c4[p].x = fmaf(fx, c4[p].x, ix * gx);
        h4[p].x = ox * tanh_(c4[p].x);
        float iy = sigf(ai[p].y), fy = sigf(af4[p].y), gy = tanh_(ag[p].y), oy = sigf(ao[p].y);
        c4[p].y = fmaf(fy, c4[p].y, iy * gy);
        h4[p].y = oy * tanh_(c4[p].y);
    }
}

__global__ void __launch_bounds__(NTHREADS, 1)
lstm_fused(const float* __restrict__ noise, const float* __restrict__ hist,
           const float* __restrict__ gap,   const float* __restrict__ W_ih,
           const float* __restrict__ W_hh,  const float* __restrict__ b_ih,
           const float* __restrict__ b_hh,  const float* __restrict__ W1,
           const float* __restrict__ b1,    const float* __restrict__ W2,
           const float* __restrict__ b2,    float* __restrict__ out) {
    extern __shared__ char smraw[];
    SMem* s = reinterpret_cast<SMem*>(smraw);

    const int tid = threadIdx.x;
    const int u   = tid >> 3;      // hidden unit
    const int pb  = tid & 7;       // row-block
    const int wid = tid >> 5;
    const int lane = tid & 31;
    const int blockRow = blockIdx.x * ROWS_PER_CTA;
    const int R = blockRow + pb * 8;   // this thread's rows: R..R+7

    // ---- stage weights (transposed, gate-packed) ----
    for (int idx = tid; idx < 76 * 64; idx += NTHREADS) {
        int k = idx >> 6, uu = idx & 63;
        float4 w;
        if (k < 12) {
            w.x = W_ih[uu * 12 + k];
            w.y = W_ih[(64 + uu) * 12 + k];
            w.z = W_ih[(128 + uu) * 12 + k];
            w.w = W_ih[(192 + uu) * 12 + k];
        } else {
            int kk = k - 12;
            w.x = W_hh[uu * 64 + kk];
            w.y = W_hh[(64 + uu) * 64 + kk];
            w.z = W_hh[(128 + uu) * 64 + kk];
            w.w = W_hh[(192 + uu) * 64 + kk];
        }
        s->wpack[k][uu] = w;
    }
    for (int idx = tid; idx < 64 * 64; idx += NTHREADS) {
        int uu = idx >> 6, k = idx & 63;
        s->w1t[k][uu] = W1[idx];
    }
    // h0 = 0 in phase 0
    for (int idx = tid; idx < 64 * 8; idx += NTHREADS) {
        int k = idx >> 3, b = idx & 7;
        s->xA[0][12 + k][b] = make_float4(0.f, 0.f, 0.f, 0.f);
        s->xB[0][12 + k][b] = make_float4(0.f, 0.f, 0.f, 0.f);
    }
    // ---- copy hist_x into out[:, :64, :] ----
    for (int idx = tid; idx < ROWS_PER_CTA * 192; idx += NTHREADS) {
        int rl = idx / 192, j = idx % 192;
        out[(size_t)(blockRow + rl) * OUTSTR + j] = hist[(size_t)(blockRow + rl) * 192 + j];
    }

    const float bi = b_ih[u] + b_hh[u];
    const float bf = b_ih[64 + u] + b_hh[64 + u];
    const float bg = b_ih[128 + u] + b_hh[128 + u];
    const float bo = b_ih[192 + u] + b_hh[192 + u];
    const float b1v = b1[u];
    const float w2v = W2[u];
    const float b2v = b2[0];

    float2 c4[4], h4[4], dist4[4], pfv[4], pfd[4];
#pragma unroll
    for (int p = 0; p < 4; ++p) {
        c4[p] = make_float2(0.f, 0.f);
        dist4[p] = make_float2(0.f, 0.f);
        pfv[p] = make_float2(0.f, 0.f);
        pfd[p] = make_float2(0.f, 0.f);
    }

    // Prefetch: pfd = hist ch2 (all threads, drives dist), pfv = this u's channel
    auto pre_cond = [&](int j) {
#pragma unroll
        for (int p = 0; p < 4; ++p) {
            const float* hp = hist + (size_t)(R + 2 * p) * 192 + j * 3;
            pfd[p].x = hp[2];
            pfd[p].y = hp[192 + 2];
            if (u < 2) {
                pfv[p].x = hp[u];
                pfv[p].y = hp[192 + u];
            }
        }
        if (u >= 4 && u < 12) {
            int ch = u - 4;
#pragma unroll
            for (int p = 0; p < 4; ++p) {
                const float* np = noise + (size_t)(R + 2 * p) * 2048 + j * 8 + ch;
                pfv[p].x = np[0];
                pfv[p].y = np[2048];
            }
        }
    };
    auto pre_gen = [&](int t) {
        if (u < 2) {
#pragma unroll
            for (int p = 0; p < 4; ++p) {
                const float* gp = gap + (size_t)(R + 2 * p) * 386 + t * 2 + u;
                pfv[p].x = gp[0];
                pfv[p].y = gp[386];
            }
        } else if (u >= 4 && u < 12) {
            if (t < 192) {
                int ch = u - 4;
#pragma unroll
                for (int p = 0; p < 4; ++p) {
                    const float* np = noise + (size_t)(R + 2 * p) * 2048 + (64 + t) * 8 + ch;
                    pfv[p].x = np[0];
                    pfv[p].y = np[2048];
                }
            } else {
#pragma unroll
                for (int p = 0; p < 4; ++p) pfv[p] = make_float2(0.f, 0.f);
            }
        }
    };
    auto write_inputs = [&](int ph) {
        if (u < 2 || (u >= 4 && u < 12)) {
            s->xA[ph][u][pb] = make_float4(pfv[0].x, pfv[0].y, pfv[1].x, pfv[1].y);
            s->xB[ph][u][pb] = make_float4(pfv[2].x, pfv[2].y, pfv[3].x, pfv[3].y);
        }
    };
    auto write_h = [&](int ph) {
        s->xA[ph][12 + u][pb] = make_float4(h4[0].x, h4[0].y, h4[1].x, h4[1].y);
        s->xB[ph][12 + u][pb] = make_float4(h4[2].x, h4[2].y, h4[3].x, h4[3].y);
    };

    pre_cond(0);
    __syncthreads();   // staging + h0 visible

    // ================= conditioning (64 steps, 1 barrier each) =================
    for (int j = 0; j < 64; ++j) {
        int ph = j & 1;
        write_inputs(ph);
        float2 x2[4];
#pragma unroll
        for (int p = 0; p < 4; ++p) {
            x2[p] = pfd[p];                 // hist ch2 (k=2 input)
            dist4[p].x += pfd[p].x;         // inclusive cumsum (k=3 input)
            dist4[p].y += pfd[p].y;
        }
        __syncthreads();                    // inputs + previous h visible
        if (j < 63) pre_cond(j + 1); else pre_gen(0);
        lstm_step4(s, u, pb, ph, x2, dist4, bi, bf, bg, bo, c4, h4);
        write_h(ph ^ 1);
    }
    __syncthreads();   // last h write visible for gen MLP

    // ================= generation (193 steps, 3 barriers each) =================
    for (int t = 0; t <= 192; ++t) {
        int ph = t & 1;
        // --- MLP head: a[u][row] = b1 + sum_k h[k][row]*W1[u][k] ---
        float2 a0 = make_float2(b1v, b1v), a1v = a0, a2 = a0, a3 = a0;
        {
            const float*  w1p = &s->w1t[0][u];
            const float4* ha  = &s->xA[ph][12][pb];
            const float4* hb  = &s->xB[ph][12][pb];
#pragma unroll 4
            for (int k = 0; k < 64; ++k) {
                float wv = w1p[k * 64];
                float4 A = ha[k * 8], B = hb[k * 8];
                gate4(wv, make_float2(A.x, A.y), make_float2(A.z, A.w),
                      make_float2(B.x, B.y), make_float2(B.z, B.w),
                      a0, a1v, a2, a3);
            }
        }
        float2 part[4];
        part[0] = make_float2(tanh_(a0.x) * w2v, tanh_(a0.y) * w2v);
        part[1] = make_float2(tanh_(a1v.x) * w2v, tanh_(a1v.y) * w2v);
        part[2] = make_float2(tanh_(a2.x) * w2v, tanh_(a2.y) * w2v);
        part[3] = make_float2(tanh_(a3.x) * w2v, tanh_(a3.y) * w2v);
        // reduce over the 4 u's in this warp (lane bits 3,4)
#pragma unroll
        for (int p = 0; p < 4; ++p) {
            part[p].x += __shfl_xor_sync(0xffffffffu, part[p].x, 8);
            part[p].y += __shfl_xor_sync(0xffffffffu, part[p].y, 8);
            part[p].x += __shfl_xor_sync(0xffffffffu, part[p].x, 16);
            part[p].y += __shfl_xor_sync(0xffffffffu, part[p].y, 16);
        }
        if (lane < 8) {
#pragma unroll
            for (int p = 0; p < 4; ++p) s->zpart[wid][pb][p] = part[p];
        }
        write_inputs(ph);                   // gap/noise for this step
        __syncthreads();                    // B: zpart + inputs ready
        if (tid < 32) {
            int pb2 = tid >> 2, p2 = tid & 3;
            float sx = b2v, sy = b2v;
#pragma unroll
            for (int w = 0; w < 16; ++w) {
                float2 z = s->zpart[w][pb2][p2];
                sx += z.x; sy += z.y;
            }
            s->dpbuf[pb2][p2] = make_float2(24.f * tanh_(sx), 24.f * tanh_(sy));
        }
        __syncthreads();                    // C: dp ready
        float2 dp[4];
#pragma unroll
        for (int p = 0; p < 4; ++p) {
            dp[p] = s->dpbuf[pb][p];
            dist4[p].x += dp[p].x;
            dist4[p].y += dp[p].y;
        }
        int trow = (64 + t) * 3;
        if (u < 2) {
#pragma unroll
            for (int p = 0; p < 4; ++p) {
                out[(size_t)(R + 2 * p) * OUTSTR + trow + u] = pfv[p].x;
                out[(size_t)(R + 2 * p + 1) * OUTSTR + trow + u] = pfv[p].y;
            }
        } else if (u == 2) {
#pragma unroll
            for (int p = 0; p < 4; ++p) {
                out[(size_t)(R + 2 * p) * OUTSTR + trow + 2] = dp[p].x;
                out[(size_t)(R + 2 * p + 1) * OUTSTR + trow + 2] = dp[p].y;
            }
        }
        if (t == 192) break;                // last LSTM update is dead in the reference
        pre_gen(t + 1);
        lstm_step4(s, u, pb, ph, dp, dist4, bi, bf, bg, bo, c4, h4);
        write_h(ph ^ 1);
        __syncthreads();                    // D: h visible for next MLP
    }
}

extern "C" void kernel_launch(void* const* d_in, const int* in_sizes, int n_in,
                              void* d_out, int out_size) {
    const float* noise = (const float*)d_in[0];
    const float* hist  = (const float*)d_in[1];
    const float* gap   = (const float*)d_in[2];
    const float* W_ih  = (const float*)d_in[3];
    const float* W_hh  = (const float*)d_in[4];
    const float* b_ih  = (const float*)d_in[5];
    const float* b_hh  = (const float*)d_in[6];
    const float* W1    = (const float*)d_in[7];
    const float* b1    = (const float*)d_in[8];
    const float* W2    = (const float*)d_in[9];
    const float* b2    = (const float*)d_in[10];
    float* out = (float*)d_out;

    size_t smem = sizeof(SMem);
    cudaFuncSetAttribute(lstm_fused, cudaFuncAttributeMaxDynamicSharedMemorySize, (int)smem);
    lstm_fused<<<NCTA, NTHREADS, smem>>>(noise, hist, gap, W_ih, W_hh, b_ih, b_hh,
                                         W1, b1, W2, b2, out);
}

// round 7
// speedup vs baseline: 1.0081x; 1.0058x over previous
#include <cuda_runtime.h>

#define NTHREADS 512
#define ROWS_PER_CTA 64
#define NCTA 128          // 8192 / 64
#define OUTSTR 771        // 257*3

// Thread layout: u = tid>>3 (hidden unit 0..63), pb = tid&7 (row-block 0..7).
// Thread owns 8 rows = 4 float2 pairs: global pairs 4pb..4pb+3.
struct SMem {
    float4 wpack[76][64];    // wpack[k][u] = {Wi,Wf,Wg,Wo}[.,k] for unit u
    float4 xA[2][76][8];     // [phase][k][pb]: pairs 4pb,4pb+1
    float4 xB[2][76][8];     // [phase][k][pb]: pairs 4pb+2,4pb+3
    float  w1t[64][64];      // w1t[k][u] = W1[u][k]
    float2 zpart[16][8][4];  // [warp][pb][pair]
    float2 dpbuf[8][4];      // [pb][pair]
};

__device__ __forceinline__ float sigf(float x) {
    return __fdividef(1.f, 1.f + __expf(-x));
}
__device__ __forceinline__ float tanh_(float x) {
    float e = __expf(2.f * x);
    return 1.f - __fdividef(2.f, e + 1.f);
}

// 4 accumulators += pair-vector * scalar, via packed fma.rn.f32x2
__device__ __forceinline__ void gate4(float sw,
                                      float2 p0, float2 p1, float2 p2, float2 p3,
                                      float2& a0, float2& a1, float2& a2, float2& a3) {
    asm("{\n\t"
        ".reg .b64 rb, rx, ra;\n\t"
        "mov.b64 rb, {%8,%8};\n\t"
        "mov.b64 rx, {%9,%10};  mov.b64 ra, {%0,%1}; fma.rn.f32x2 ra, rx, rb, ra; mov.b64 {%0,%1}, ra;\n\t"
        "mov.b64 rx, {%11,%12}; mov.b64 ra, {%2,%3}; fma.rn.f32x2 ra, rx, rb, ra; mov.b64 {%2,%3}, ra;\n\t"
        "mov.b64 rx, {%13,%14}; mov.b64 ra, {%4,%5}; fma.rn.f32x2 ra, rx, rb, ra; mov.b64 {%4,%5}, ra;\n\t"
        "mov.b64 rx, {%15,%16}; mov.b64 ra, {%6,%7}; fma.rn.f32x2 ra, rx, rb, ra; mov.b64 {%6,%7}, ra;\n\t"
        "}"
        : "+f"(a0.x), "+f"(a0.y), "+f"(a1.x), "+f"(a1.y),
          "+f"(a2.x), "+f"(a2.y), "+f"(a3.x), "+f"(a3.y)
        : "f"(sw),
          "f"(p0.x), "f"(p0.y), "f"(p1.x), "f"(p1.y),
          "f"(p2.x), "f"(p2.y), "f"(p3.x), "f"(p3.y));
}

// LSTM cell. XREG: k=2 (x2) and k=3 (x3) come from registers (gen phase);
// otherwise all 76 k come from SMEM phase ph (cond phase).
template<bool XREG>
__device__ __forceinline__ void lstm_step4(const SMem* s, int u, int pb, int ph,
                                           const float2 x2[4], const float2 x3[4],
                                           float bi, float bf, float bg, float bo,
                                           float2 c4[4], float2 h4[4]) {
    float2 ai[4], af4[4], ag[4], ao[4];
#pragma unroll
    for (int p = 0; p < 4; ++p) {
        ai[p] = make_float2(bi, bi);
        af4[p] = make_float2(bf, bf);
        ag[p] = make_float2(bg, bg);
        ao[p] = make_float2(bo, bo);
    }
    const float4* wp = &s->wpack[0][u];
    const float4* xa = &s->xA[ph][0][pb];
    const float4* xb = &s->xB[ph][0][pb];

    auto doK = [&](float4 w, float4 A, float4 B) {
        float2 p0 = make_float2(A.x, A.y), p1 = make_float2(A.z, A.w);
        float2 p2 = make_float2(B.x, B.y), p3 = make_float2(B.z, B.w);
        gate4(w.x, p0, p1, p2, p3, ai[0], ai[1], ai[2], ai[3]);
        gate4(w.y, p0, p1, p2, p3, af4[0], af4[1], af4[2], af4[3]);
        gate4(w.z, p0, p1, p2, p3, ag[0], ag[1], ag[2], ag[3]);
        gate4(w.w, p0, p1, p2, p3, ao[0], ao[1], ao[2], ao[3]);
    };
    auto doKreg = [&](float4 w, const float2 x[4]) {
        gate4(w.x, x[0], x[1], x[2], x[3], ai[0], ai[1], ai[2], ai[3]);
        gate4(w.y, x[0], x[1], x[2], x[3], af4[0], af4[1], af4[2], af4[3]);
        gate4(w.z, x[0], x[1], x[2], x[3], ag[0], ag[1], ag[2], ag[3]);
        gate4(w.w, x[0], x[1], x[2], x[3], ao[0], ao[1], ao[2], ao[3]);
    };

    doK(wp[0], xa[0], xb[0]);        // k=0
    doK(wp[64], xa[8], xb[8]);       // k=1
    if (XREG) {
        doKreg(wp[2 * 64], x2);
        doKreg(wp[3 * 64], x3);
    } else {
        doK(wp[2 * 64], xa[16], xb[16]);
        doK(wp[3 * 64], xa[24], xb[24]);
    }
#pragma unroll 4
    for (int k = 4; k < 76; ++k)
        doK(wp[k * 64], xa[k * 8], xb[k * 8]);

#pragma unroll
    for (int p = 0; p < 4; ++p) {
        float ix = sigf(ai[p].x), fx = sigf(af4[p].x), gx = tanh_(ag[p].x), ox = sigf(ao[p].x);
        c4[p].x = fmaf(fx, c4[p].x, ix * gx);
        h4[p].x = ox * tanh_(c4[p].x);
        float iy = sigf(ai[p].y), fy = sigf(af4[p].y), gy = tanh_(ag[p].y), oy = sigf(ao[p].y);
        c4[p].y = fmaf(fy, c4[p].y, iy * gy);
        h4[p].y = oy * tanh_(c4[p].y);
    }
}

__global__ void __launch_bounds__(NTHREADS, 1)
lstm_fused(const float* __restrict__ noise, const float* __restrict__ hist,
           const float* __restrict__ gap,   const float* __restrict__ W_ih,
           const float* __restrict__ W_hh,  const float* __restrict__ b_ih,
           const float* __restrict__ b_hh,  const float* __restrict__ W1,
           const float* __restrict__ b1,    const float* __restrict__ W2,
           const float* __restrict__ b2,    float* __restrict__ out) {
    extern __shared__ char smraw[];
    SMem* s = reinterpret_cast<SMem*>(smraw);

    const int tid = threadIdx.x;
    const int u   = tid >> 3;      // hidden unit
    const int pb  = tid & 7;       // row-block
    const int wid = tid >> 5;
    const int lane = tid & 31;
    const int blockRow = blockIdx.x * ROWS_PER_CTA;
    const int R = blockRow + pb * 8;   // this thread's rows: R..R+7

    // ---- stage weights (transposed, gate-packed) ----
    for (int idx = tid; idx < 76 * 64; idx += NTHREADS) {
        int k = idx >> 6, uu = idx & 63;
        float4 w;
        if (k < 12) {
            w.x = W_ih[uu * 12 + k];
            w.y = W_ih[(64 + uu) * 12 + k];
            w.z = W_ih[(128 + uu) * 12 + k];
            w.w = W_ih[(192 + uu) * 12 + k];
        } else {
            int kk = k - 12;
            w.x = W_hh[uu * 64 + kk];
            w.y = W_hh[(64 + uu) * 64 + kk];
            w.z = W_hh[(128 + uu) * 64 + kk];
            w.w = W_hh[(192 + uu) * 64 + kk];
        }
        s->wpack[k][uu] = w;
    }
    for (int idx = tid; idx < 64 * 64; idx += NTHREADS) {
        int uu = idx >> 6, k = idx & 63;
        s->w1t[k][uu] = W1[idx];
    }
    // h0 = 0 in phase 0
    for (int idx = tid; idx < 64 * 8; idx += NTHREADS) {
        int k = idx >> 3, b = idx & 7;
        s->xA[0][12 + k][b] = make_float4(0.f, 0.f, 0.f, 0.f);
        s->xB[0][12 + k][b] = make_float4(0.f, 0.f, 0.f, 0.f);
    }
    // ---- copy hist_x into out[:, :64, :] ----
    for (int idx = tid; idx < ROWS_PER_CTA * 192; idx += NTHREADS) {
        int rl = idx / 192, j = idx % 192;
        out[(size_t)(blockRow + rl) * OUTSTR + j] = hist[(size_t)(blockRow + rl) * 192 + j];
    }

    const float bi = b_ih[u] + b_hh[u];
    const float bf = b_ih[64 + u] + b_hh[64 + u];
    const float bg = b_ih[128 + u] + b_hh[128 + u];
    const float bo = b_ih[192 + u] + b_hh[192 + u];
    const float b1v = b1[u];
    const float w2v = W2[u];
    const float b2v = b2[0];

    float2 c4[4], h4[4], dist4[4], pfv[4];
#pragma unroll
    for (int p = 0; p < 4; ++p) {
        c4[p] = make_float2(0.f, 0.f);
        dist4[p] = make_float2(0.f, 0.f);
        pfv[p] = make_float2(0.f, 0.f);
    }

    // ---- prefetchers: only u<12 threads touch global memory ----
    auto pre_cond = [&](int j) {
        if (u < 4) {
            int ch = (u == 3) ? 2 : u;   // u==3 tracks ch2 to build dist
#pragma unroll
            for (int p = 0; p < 4; ++p) {
                const float* hp = hist + (size_t)(R + 2 * p) * 192 + j * 3 + ch;
                pfv[p].x = hp[0];
                pfv[p].y = hp[192];
            }
        } else if (u < 12) {
            int ch = u - 4;
#pragma unroll
            for (int p = 0; p < 4; ++p) {
                const float* np = noise + (size_t)(R + 2 * p) * 2048 + j * 8 + ch;
                pfv[p].x = np[0];
                pfv[p].y = np[2048];
            }
        }
    };
    auto pre_gen = [&](int t) {
        if (u < 2) {
#pragma unroll
            for (int p = 0; p < 4; ++p) {
                const float* gp = gap + (size_t)(R + 2 * p) * 386 + t * 2 + u;
                pfv[p].x = gp[0];
                pfv[p].y = gp[386];
            }
        } else if (u >= 4 && u < 12) {
            if (t < 192) {
                int ch = u - 4;
#pragma unroll
                for (int p = 0; p < 4; ++p) {
                    const float* np = noise + (size_t)(R + 2 * p) * 2048 + (64 + t) * 8 + ch;
                    pfv[p].x = np[0];
                    pfv[p].y = np[2048];
                }
            } else {
#pragma unroll
                for (int p = 0; p < 4; ++p) pfv[p] = make_float2(0.f, 0.f);
            }
        }
    };
    auto write_h = [&](int ph) {
        s->xA[ph][12 + u][pb] = make_float4(h4[0].x, h4[0].y, h4[1].x, h4[1].y);
        s->xB[ph][12 + u][pb] = make_float4(h4[2].x, h4[2].y, h4[3].x, h4[3].y);
    };

    pre_cond(0);
    __syncthreads();   // staging + h0 visible

    // ================= conditioning (64 steps, 1 barrier each) =================
    for (int j = 0; j < 64; ++j) {
        int ph = j & 1;
        if (u == 3) {            // dist = inclusive cumsum of ch2
#pragma unroll
            for (int p = 0; p < 4; ++p) {
                dist4[p].x += pfv[p].x;
                dist4[p].y += pfv[p].y;
            }
            s->xA[ph][3][pb] = make_float4(dist4[0].x, dist4[0].y, dist4[1].x, dist4[1].y);
            s->xB[ph][3][pb] = make_float4(dist4[2].x, dist4[2].y, dist4[3].x, dist4[3].y);
        } else if (u < 12) {
            s->xA[ph][u][pb] = make_float4(pfv[0].x, pfv[0].y, pfv[1].x, pfv[1].y);
            s->xB[ph][u][pb] = make_float4(pfv[2].x, pfv[2].y, pfv[3].x, pfv[3].y);
        }
        __syncthreads();                    // inputs + previous h visible
        if (j < 63) pre_cond(j + 1); else pre_gen(0);
        lstm_step4<false>(s, u, pb, ph, nullptr, nullptr, bi, bf, bg, bo, c4, h4);
        write_h(ph ^ 1);
    }
    __syncthreads();   // last h + last dist visible

    // all threads pick up final dist from smem (phase of j=63 is 1)
    {
        float4 A = s->xA[1][3][pb], B = s->xB[1][3][pb];
        dist4[0] = make_float2(A.x, A.y);
        dist4[1] = make_float2(A.z, A.w);
        dist4[2] = make_float2(B.x, B.y);
        dist4[3] = make_float2(B.z, B.w);
    }

    // ================= generation (193 steps, 3 barriers each) =================
    for (int t = 0; t <= 192; ++t) {
        int ph = t & 1;
        // --- MLP head: a[u][row] = b1 + sum_k h[k][row]*W1[u][k] ---
        float2 a0 = make_float2(b1v, b1v), a1v = a0, a2 = a0, a3 = a0;
        {
            const float*  w1p = &s->w1t[0][u];
            const float4* ha  = &s->xA[ph][12][pb];
            const float4* hb  = &s->xB[ph][12][pb];
#pragma unroll 4
            for (int k = 0; k < 64; ++k) {
                float wv = w1p[k * 64];
                float4 A = ha[k * 8], B = hb[k * 8];
                gate4(wv, make_float2(A.x, A.y), make_float2(A.z, A.w),
                      make_float2(B.x, B.y), make_float2(B.z, B.w),
                      a0, a1v, a2, a3);
            }
        }
        float2 part[4];
        part[0] = make_float2(tanh_(a0.x) * w2v, tanh_(a0.y) * w2v);
        part[1] = make_float2(tanh_(a1v.x) * w2v, tanh_(a1v.y) * w2v);
        part[2] = make_float2(tanh_(a2.x) * w2v, tanh_(a2.y) * w2v);
        part[3] = make_float2(tanh_(a3.x) * w2v, tanh_(a3.y) * w2v);
        // reduce over the 4 u's in this warp (lane bits 3,4)
#pragma unroll
        for (int p = 0; p < 4; ++p) {
            part[p].x += __shfl_xor_sync(0xffffffffu, part[p].x, 8);
            part[p].y += __shfl_xor_sync(0xffffffffu, part[p].y, 8);
            part[p].x += __shfl_xor_sync(0xffffffffu, part[p].x, 16);
            part[p].y += __shfl_xor_sync(0xffffffffu, part[p].y, 16);
        }
        if (lane < 8) {
#pragma unroll
            for (int p = 0; p < 4; ++p) s->zpart[wid][pb][p] = part[p];
        }
        // write gap/noise inputs for this step
        if (u < 2 || (u >= 4 && u < 12)) {
            s->xA[ph][u][pb] = make_float4(pfv[0].x, pfv[0].y, pfv[1].x, pfv[1].y);
            s->xB[ph][u][pb] = make_float4(pfv[2].x, pfv[2].y, pfv[3].x, pfv[3].y);
        }
        __syncthreads();                    // B: zpart + inputs ready
        if (tid < 32) {
            int pb2 = tid >> 2, p2 = tid & 3;
            float sx = b2v, sy = b2v;
#pragma unroll
            for (int w = 0; w < 16; ++w) {
                float2 z = s->zpart[w][pb2][p2];
                sx += z.x; sy += z.y;
            }
            s->dpbuf[pb2][p2] = make_float2(24.f * tanh_(sx), 24.f * tanh_(sy));
        }
        __syncthreads();                    // C: dp ready
        float2 dp[4];
#pragma unroll
        for (int p = 0; p < 4; ++p) {
            dp[p] = s->dpbuf[pb][p];
            dist4[p].x += dp[p].x;
            dist4[p].y += dp[p].y;
        }
        int trow = (64 + t) * 3;
        if (u < 2) {
#pragma unroll
            for (int p = 0; p < 4; ++p) {
                out[(size_t)(R + 2 * p) * OUTSTR + trow + u] = pfv[p].x;
                out[(size_t)(R + 2 * p + 1) * OUTSTR + trow + u] = pfv[p].y;
            }
        } else if (u == 2) {
#pragma unroll
            for (int p = 0; p < 4; ++p) {
                out[(size_t)(R + 2 * p) * OUTSTR + trow + 2] = dp[p].x;
                out[(size_t)(R + 2 * p + 1) * OUTSTR + trow + 2] = dp[p].y;
            }
        }
        if (t == 192) break;                // last LSTM update is dead in the reference
        pre_gen(t + 1);
        lstm_step4<true>(s, u, pb, ph, dp, dist4, bi, bf, bg, bo, c4, h4);
        write_h(ph ^ 1);
        __syncthreads();                    // D: h visible for next MLP
    }
}

extern "C" void kernel_launch(void* const* d_in, const int* in_sizes, int n_in,
                              void* d_out, int out_size) {
    const float* noise = (const float*)d_in[0];
    const float* hist  = (const float*)d_in[1];
    const float* gap   = (const float*)d_in[2];
    const float* W_ih  = (const float*)d_in[3];
    const float* W_hh  = (const float*)d_in[4];
    const float* b_ih  = (const float*)d_in[5];
    const float* b_hh  = (const float*)d_in[6];
    const float* W1    = (const float*)d_in[7];
    const float* b1    = (const float*)d_in[8];
    const float* W2    = (const float*)d_in[9];
    const float* b2    = (const float*)d_in[10];
    float* out = (float*)d_out;

    size_t smem = sizeof(SMem);
    cudaFuncSetAttribute(lstm_fused, cudaFuncAttributeMaxDynamicSharedMemorySize, (int)smem);
    lstm_fused<<<NCTA, NTHREADS, smem>>>(noise, hist, gap, W_ih, W_hh, b_ih, b_hh,
                                         W1, b1, W2, b2, out);
}

// round 8
// speedup vs baseline: 1.1581x; 1.1487x over previous
#include <cuda_runtime.h>

#define NTHREADS 512
#define ROWS_PER_CTA 64
#define NCTA 128          // 8192 / 64
#define OUTSTR 771        // 257*3

// Thread layout (R3): u = tid & 63 (hidden unit), q = tid >> 6 (row group 0..7).
// Thread owns 8 rows R..R+7 (R = blockRow + 8q) as 4 float2 pairs.
// Warp = 32 consecutive u, same q  -> x reads are warp-uniform broadcasts.
struct SMem {
    float4 wpack[76][64];   // wpack[k][u] = {Wi,Wf,Wg,Wo}[.,k] for unit u   (77824 B)
    float4 xA[2][76][9];    // [phase][k][q] pairs 0,1 (pad 9 -> 144B k-stride)
    float4 xB[2][76][9];    // [phase][k][q] pairs 2,3
    float  w1t[64][64];     // w1t[k][u] = W1[u][k]
    float2 zhalf[8][2][4];  // [q][warp-half][pair]
};

__device__ __forceinline__ float sigf(float x) {
    return __fdividef(1.f, 1.f + __expf(-x));
}
__device__ __forceinline__ float tanh_(float x) {
    float e = __expf(2.f * x);
    return 1.f - __fdividef(2.f, e + 1.f);
}

// 4 accumulators += pair-vector * scalar, via packed fma.rn.f32x2
__device__ __forceinline__ void gate4(float sw,
                                      float2 p0, float2 p1, float2 p2, float2 p3,
                                      float2& a0, float2& a1, float2& a2, float2& a3) {
    asm("{\n\t"
        ".reg .b64 rb, rx, ra;\n\t"
        "mov.b64 rb, {%8,%8};\n\t"
        "mov.b64 rx, {%9,%10};  mov.b64 ra, {%0,%1}; fma.rn.f32x2 ra, rx, rb, ra; mov.b64 {%0,%1}, ra;\n\t"
        "mov.b64 rx, {%11,%12}; mov.b64 ra, {%2,%3}; fma.rn.f32x2 ra, rx, rb, ra; mov.b64 {%2,%3}, ra;\n\t"
        "mov.b64 rx, {%13,%14}; mov.b64 ra, {%4,%5}; fma.rn.f32x2 ra, rx, rb, ra; mov.b64 {%4,%5}, ra;\n\t"
        "mov.b64 rx, {%15,%16}; mov.b64 ra, {%6,%7}; fma.rn.f32x2 ra, rx, rb, ra; mov.b64 {%6,%7}, ra;\n\t"
        "}"
        : "+f"(a0.x), "+f"(a0.y), "+f"(a1.x), "+f"(a1.y),
          "+f"(a2.x), "+f"(a2.y), "+f"(a3.x), "+f"(a3.y)
        : "f"(sw),
          "f"(p0.x), "f"(p0.y), "f"(p1.x), "f"(p1.y),
          "f"(p2.x), "f"(p2.y), "f"(p3.x), "f"(p3.y));
}

// LSTM cell. XREG: k=2 (x2) / k=3 (x3) from registers (gen); else from SMEM phase ph.
// Inner loop is software-pipelined: prefetch k+1 operands while k's FMAs issue.
template<bool XREG>
__device__ __forceinline__ void lstm_step4(const SMem* s, int u, int q, int ph,
                                           const float2 x2[4], const float2 x3[4],
                                           float bi, float bf, float bg, float bo,
                                           float2 c4[4], float2 h4[4]) {
    float2 ai[4], af4[4], ag[4], ao[4];
#pragma unroll
    for (int p = 0; p < 4; ++p) {
        ai[p] = make_float2(bi, bi);
        af4[p] = make_float2(bf, bf);
        ag[p] = make_float2(bg, bg);
        ao[p] = make_float2(bo, bo);
    }
    const float4* wp = &s->wpack[0][u];   // stride 64 float4
    const float4* xa = &s->xA[ph][0][q];  // stride 9 float4
    const float4* xb = &s->xB[ph][0][q];

    auto doK = [&](float4 w, float4 A, float4 B) {
        float2 p0 = make_float2(A.x, A.y), p1 = make_float2(A.z, A.w);
        float2 p2 = make_float2(B.x, B.y), p3 = make_float2(B.z, B.w);
        gate4(w.x, p0, p1, p2, p3, ai[0], ai[1], ai[2], ai[3]);
        gate4(w.y, p0, p1, p2, p3, af4[0], af4[1], af4[2], af4[3]);
        gate4(w.z, p0, p1, p2, p3, ag[0], ag[1], ag[2], ag[3]);
        gate4(w.w, p0, p1, p2, p3, ao[0], ao[1], ao[2], ao[3]);
    };
    auto doKreg = [&](float4 w, const float2 x[4]) {
        gate4(w.x, x[0], x[1], x[2], x[3], ai[0], ai[1], ai[2], ai[3]);
        gate4(w.y, x[0], x[1], x[2], x[3], af4[0], af4[1], af4[2], af4[3]);
        gate4(w.z, x[0], x[1], x[2], x[3], ag[0], ag[1], ag[2], ag[3]);
        gate4(w.w, x[0], x[1], x[2], x[3], ao[0], ao[1], ao[2], ao[3]);
    };

    doK(wp[0], xa[0], xb[0]);            // k=0
    doK(wp[64], xa[9], xb[9]);           // k=1
    if (XREG) {
        doKreg(wp[2 * 64], x2);          // k=2 (dp)
        doKreg(wp[3 * 64], x3);          // k=3 (dist)
    } else {
        doK(wp[2 * 64], xa[18], xb[18]);
        doK(wp[3 * 64], xa[27], xb[27]);
    }
    // pipelined k = 4..75
    float4 wc = wp[4 * 64], ac = xa[4 * 9], bc = xb[4 * 9];
#pragma unroll 4
    for (int k = 4; k < 75; ++k) {
        float4 wn = wp[(k + 1) * 64];
        float4 an = xa[(k + 1) * 9];
        float4 bn = xb[(k + 1) * 9];
        doK(wc, ac, bc);
        wc = wn; ac = an; bc = bn;
    }
    doK(wc, ac, bc);                     // k=75

#pragma unroll
    for (int p = 0; p < 4; ++p) {
        float ix = sigf(ai[p].x), fx = sigf(af4[p].x), gx = tanh_(ag[p].x), ox = sigf(ao[p].x);
        c4[p].x = fmaf(fx, c4[p].x, ix * gx);
        h4[p].x = ox * tanh_(c4[p].x);
        float iy = sigf(ai[p].y), fy = sigf(af4[p].y), gy = tanh_(ag[p].y), oy = sigf(ao[p].y);
        c4[p].y = fmaf(fy, c4[p].y, iy * gy);
        h4[p].y = oy * tanh_(c4[p].y);
    }
}

__global__ void __launch_bounds__(NTHREADS, 1)
lstm_fused(const float* __restrict__ noise, const float* __restrict__ hist,
           const float* __restrict__ gap,   const float* __restrict__ W_ih,
           const float* __restrict__ W_hh,  const float* __restrict__ b_ih,
           const float* __restrict__ b_hh,  const float* __restrict__ W1,
           const float* __restrict__ b1,    const float* __restrict__ W2,
           const float* __restrict__ b2,    float* __restrict__ out) {
    extern __shared__ char smraw[];
    SMem* s = reinterpret_cast<SMem*>(smraw);

    const int tid = threadIdx.x;
    const int u   = tid & 63;          // hidden unit
    const int q   = tid >> 6;          // row group
    const int lane = tid & 31;
    const int wh  = (tid >> 5) & 1;    // warp half (u<32 vs u>=32)
    const int blockRow = blockIdx.x * ROWS_PER_CTA;
    const int R = blockRow + 8 * q;    // rows R..R+7

    // ---- stage weights (transposed, gate-packed) ----
    for (int idx = tid; idx < 76 * 64; idx += NTHREADS) {
        int k = idx >> 6, uu = idx & 63;
        float4 w;
        if (k < 12) {
            w.x = W_ih[uu * 12 + k];
            w.y = W_ih[(64 + uu) * 12 + k];
            w.z = W_ih[(128 + uu) * 12 + k];
            w.w = W_ih[(192 + uu) * 12 + k];
        } else {
            int kk = k - 12;
            w.x = W_hh[uu * 64 + kk];
            w.y = W_hh[(64 + uu) * 64 + kk];
            w.z = W_hh[(128 + uu) * 64 + kk];
            w.w = W_hh[(192 + uu) * 64 + kk];
        }
        s->wpack[k][uu] = w;
    }
    for (int idx = tid; idx < 64 * 64; idx += NTHREADS) {
        int uu = idx >> 6, k = idx & 63;
        s->w1t[k][uu] = W1[idx];
    }
    // h0 = 0 in phase 0
    s->xA[0][12 + u][q] = make_float4(0.f, 0.f, 0.f, 0.f);
    s->xB[0][12 + u][q] = make_float4(0.f, 0.f, 0.f, 0.f);
    // ---- copy hist_x into out[:, :64, :] ----
    for (int idx = tid; idx < ROWS_PER_CTA * 192; idx += NTHREADS) {
        int rl = idx / 192, j = idx % 192;
        out[(size_t)(blockRow + rl) * OUTSTR + j] = hist[(size_t)(blockRow + rl) * 192 + j];
    }

    const float bi = b_ih[u] + b_hh[u];
    const float bf = b_ih[64 + u] + b_hh[64 + u];
    const float bg = b_ih[128 + u] + b_hh[128 + u];
    const float bo = b_ih[192 + u] + b_hh[192 + u];
    const float b1v = b1[u];
    const float w2v = W2[u];
    const float b2v = b2[0];

    float2 c4[4], h4[4], dist4[4], pfv[4];
#pragma unroll
    for (int p = 0; p < 4; ++p) {
        c4[p] = make_float2(0.f, 0.f);
        dist4[p] = make_float2(0.f, 0.f);
        pfv[p] = make_float2(0.f, 0.f);
    }

    // ---- prefetchers: only u<12 threads touch global memory ----
    auto pre_cond = [&](int j) {
        if (u < 4) {
            int ch = (u == 3) ? 2 : u;      // u==3 tracks ch2 for the dist cumsum
#pragma unroll
            for (int p = 0; p < 4; ++p) {
                const float* hp = hist + (size_t)(R + 2 * p) * 192 + j * 3 + ch;
                pfv[p].x = hp[0];
                pfv[p].y = hp[192];
            }
        } else if (u < 12) {
            int ch = u - 4;
#pragma unroll
            for (int p = 0; p < 4; ++p) {
                const float* np = noise + (size_t)(R + 2 * p) * 2048 + j * 8 + ch;
                pfv[p].x = np[0];
                pfv[p].y = np[2048];
            }
        }
    };
    auto pre_gen = [&](int t) {
        if (u < 2) {
#pragma unroll
            for (int p = 0; p < 4; ++p) {
                const float* gp = gap + (size_t)(R + 2 * p) * 386 + t * 2 + u;
                pfv[p].x = gp[0];
                pfv[p].y = gp[386];
            }
        } else if (u >= 4 && u < 12) {
            if (t < 192) {
                int ch = u - 4;
#pragma unroll
                for (int p = 0; p < 4; ++p) {
                    const float* np = noise + (size_t)(R + 2 * p) * 2048 + (64 + t) * 8 + ch;
                    pfv[p].x = np[0];
                    pfv[p].y = np[2048];
                }
            } else {
#pragma unroll
                for (int p = 0; p < 4; ++p) pfv[p] = make_float2(0.f, 0.f);
            }
        }
    };
    auto write_h = [&](int ph) {
        s->xA[ph][12 + u][q] = make_float4(h4[0].x, h4[0].y, h4[1].x, h4[1].y);
        s->xB[ph][12 + u][q] = make_float4(h4[2].x, h4[2].y, h4[3].x, h4[3].y);
    };

    pre_cond(0);
    __syncthreads();   // staging + h0 visible

    // ================= conditioning (64 steps, 1 barrier each) =================
    for (int j = 0; j < 64; ++j) {
        int ph = j & 1;
        if (u == 3) {                     // dist = inclusive cumsum of hist ch2
#pragma unroll
            for (int p = 0; p < 4; ++p) {
                dist4[p].x += pfv[p].x;
                dist4[p].y += pfv[p].y;
            }
            s->xA[ph][3][q] = make_float4(dist4[0].x, dist4[0].y, dist4[1].x, dist4[1].y);
            s->xB[ph][3][q] = make_float4(dist4[2].x, dist4[2].y, dist4[3].x, dist4[3].y);
        } else if (u < 12) {
            s->xA[ph][u][q] = make_float4(pfv[0].x, pfv[0].y, pfv[1].x, pfv[1].y);
            s->xB[ph][u][q] = make_float4(pfv[2].x, pfv[2].y, pfv[3].x, pfv[3].y);
        }
        __syncthreads();                  // inputs + previous h visible
        if (j < 63) pre_cond(j + 1); else pre_gen(0);
        lstm_step4<false>(s, u, q, ph, nullptr, nullptr, bi, bf, bg, bo, c4, h4);
        write_h(ph ^ 1);
    }
    __syncthreads();   // last h (phase 0) + last dist (phase 1) visible

    // all threads pick up final dist from phase 1
    {
        float4 A = s->xA[1][3][q], B = s->xB[1][3][q];
        dist4[0] = make_float2(A.x, A.y);
        dist4[1] = make_float2(A.z, A.w);
        dist4[2] = make_float2(B.x, B.y);
        dist4[3] = make_float2(B.z, B.w);
    }

    // ================= generation (193 steps, 2 barriers each) =================
    for (int t = 0; t <= 192; ++t) {
        int ph = t & 1;
        // --- MLP head: a[u][row] = b1 + sum_k h[k][row]*W1[u][k] ---
        float2 a0 = make_float2(b1v, b1v), a1v = a0, a2 = a0, a3 = a0;
        {
            const float*  w1p = &s->w1t[0][u];
            const float4* ha  = &s->xA[ph][12][q];
            const float4* hb  = &s->xB[ph][12][q];
#pragma unroll 4
            for (int k = 0; k < 64; ++k) {
                float wv = w1p[k * 64];
                float4 A = ha[k * 9], B = hb[k * 9];
                gate4(wv, make_float2(A.x, A.y), make_float2(A.z, A.w),
                      make_float2(B.x, B.y), make_float2(B.z, B.w),
                      a0, a1v, a2, a3);
            }
        }
        float2 part[4];
        part[0] = make_float2(tanh_(a0.x) * w2v, tanh_(a0.y) * w2v);
        part[1] = make_float2(tanh_(a1v.x) * w2v, tanh_(a1v.y) * w2v);
        part[2] = make_float2(tanh_(a2.x) * w2v, tanh_(a2.y) * w2v);
        part[3] = make_float2(tanh_(a3.x) * w2v, tanh_(a3.y) * w2v);
        // reduce over this warp's 32 u's (all lanes share q)
#pragma unroll
        for (int p = 0; p < 4; ++p) {
#pragma unroll
            for (int m = 16; m >= 1; m >>= 1) {
                part[p].x += __shfl_xor_sync(0xffffffffu, part[p].x, m);
                part[p].y += __shfl_xor_sync(0xffffffffu, part[p].y, m);
            }
        }
        if (lane == 0) {
#pragma unroll
            for (int p = 0; p < 4; ++p) s->zhalf[q][wh][p] = part[p];
        }
        // write gap/noise inputs for this step before the same barrier
        if (u < 2 || (u >= 4 && u < 12)) {
            s->xA[ph][u][q] = make_float4(pfv[0].x, pfv[0].y, pfv[1].x, pfv[1].y);
            s->xB[ph][u][q] = make_float4(pfv[2].x, pfv[2].y, pfv[3].x, pfv[3].y);
        }
        __syncthreads();                  // zhalf + x inputs visible
        // every thread computes dp for its rows (redundant but cheap)
        float2 dp[4];
#pragma unroll
        for (int p = 0; p < 4; ++p) {
            float2 za = s->zhalf[q][0][p];
            float2 zb = s->zhalf[q][1][p];
            dp[p].x = 24.f * tanh_(za.x + zb.x + b2v);
            dp[p].y = 24.f * tanh_(za.y + zb.y + b2v);
            dist4[p].x += dp[p].x;
            dist4[p].y += dp[p].y;
        }
        int trow = (64 + t) * 3;
        if (u < 2) {
#pragma unroll
            for (int p = 0; p < 4; ++p) {
                out[(size_t)(R + 2 * p) * OUTSTR + trow + u] = pfv[p].x;
                out[(size_t)(R + 2 * p + 1) * OUTSTR + trow + u] = pfv[p].y;
            }
        } else if (u == 2) {
#pragma unroll
            for (int p = 0; p < 4; ++p) {
                out[(size_t)(R + 2 * p) * OUTSTR + trow + 2] = dp[p].x;
                out[(size_t)(R + 2 * p + 1) * OUTSTR + trow + 2] = dp[p].y;
            }
        }
        if (t == 192) break;              // last LSTM update is dead in the reference
        pre_gen(t + 1);
        lstm_step4<true>(s, u, q, ph, dp, dist4, bi, bf, bg, bo, c4, h4);
        write_h(ph ^ 1);
        __syncthreads();                  // h visible for next MLP
    }
}

extern "C" void kernel_launch(void* const* d_in, const int* in_sizes, int n_in,
                              void* d_out, int out_size) {
    const float* noise = (const float*)d_in[0];
    const float* hist  = (const float*)d_in[1];
    const float* gap   = (const float*)d_in[2];
    const float* W_ih  = (const float*)d_in[3];
    const float* W_hh  = (const float*)d_in[4];
    const float* b_ih  = (const float*)d_in[5];
    const float* b_hh  = (const float*)d_in[6];
    const float* W1    = (const float*)d_in[7];
    const float* b1    = (const float*)d_in[8];
    const float* W2    = (const float*)d_in[9];
    const float* b2    = (const float*)d_in[10];
    float* out = (float*)d_out;

    size_t smem = sizeof(SMem);
    cudaFuncSetAttribute(lstm_fused, cudaFuncAttributeMaxDynamicSharedMemorySize, (int)smem);
    lstm_fused<<<NCTA, NTHREADS, smem>>>(noise, hist, gap, W_ih, W_hh, b_ih, b_hh,
                                         W1, b1, W2, b2, out);
}